// round 12
// baseline (speedup 1.0000x reference)
#include <cuda_runtime.h>
#include <cuda_fp16.h>
#include <cstdint>
#include <cstddef>

#define BATCH 64
#define N1 1024
#define N2 512
#define F0K 512
#define F1K 384

// ---------------------------------------------------------------------------
// Scratch
// ---------------------------------------------------------------------------
__device__ __half g_h0hi[(size_t)BATCH * N1 * 256];
__device__ __half g_h0lo[(size_t)BATCH * N1 * 256];
__device__ __half g_h1hi[(size_t)BATCH * N2 * 256];
__device__ __half g_h1lo[(size_t)BATCH * N2 * 256];
__device__ float g_eA[BATCH * N1];
__device__ float g_eB[BATCH * N1];
__device__ float g_eC[BATCH * N2];
__device__ float g_eD[BATCH * N2];
__device__ float g_eE[BATCH * N1];
__device__ float g_eF[BATCH * N2];
__device__ float g_mx[4 * BATCH];
__device__ float g_P2[2 * BATCH * (N1 + N2)];
__device__ float g_Q2[2 * BATCH * (N1 + N2)];

// P2/Q2 segment offsets
#define PQ_O0 ((size_t)0)
#define PQ_O1 ((size_t)BATCH * N1)
#define PQ_O2 (PQ_O1 + (size_t)BATCH * N2)
#define PQ_O3 (PQ_O2 + (size_t)BATCH * N1)
// output segment offsets
#define OO_00 ((size_t)0)
#define OO_01 ((size_t)BATCH * N1 * 256)
#define OO_10 (OO_01 + (size_t)BATCH * N1 * 256)
#define OO_11 (OO_10 + (size_t)BATCH * N2 * 256)

// ---------------------------------------------------------------------------
// mma.sync / ldmatrix / cp.async helpers (sm_80 PTX, valid at base sm_103)
// ---------------------------------------------------------------------------
__device__ __forceinline__ void ldsm4(uint32_t* d, const void* p) {
    uint32_t a = (uint32_t)__cvta_generic_to_shared(p);
    asm volatile("ldmatrix.sync.aligned.m8n8.x4.shared.b16 {%0,%1,%2,%3}, [%4];"
                 : "=r"(d[0]), "=r"(d[1]), "=r"(d[2]), "=r"(d[3]) : "r"(a));
}
__device__ __forceinline__ void ldsm4t(uint32_t* d, const void* p) {
    uint32_t a = (uint32_t)__cvta_generic_to_shared(p);
    asm volatile("ldmatrix.sync.aligned.m8n8.x4.trans.shared.b16 {%0,%1,%2,%3}, [%4];"
                 : "=r"(d[0]), "=r"(d[1]), "=r"(d[2]), "=r"(d[3]) : "r"(a));
}
__device__ __forceinline__ void mma16816(float* c, const uint32_t* a,
                                         uint32_t b0, uint32_t b1) {
    asm volatile(
        "mma.sync.aligned.m16n8k16.row.col.f32.f16.f16.f32 "
        "{%0,%1,%2,%3}, {%4,%5,%6,%7}, {%8,%9}, {%0,%1,%2,%3};"
        : "+f"(c[0]), "+f"(c[1]), "+f"(c[2]), "+f"(c[3])
        : "r"(a[0]), "r"(a[1]), "r"(a[2]), "r"(a[3]), "r"(b0), "r"(b1));
}
__device__ __forceinline__ void cp16(uint32_t dst, const void* src) {
    asm volatile("cp.async.cg.shared.global [%0], [%1], 16;"
                 :: "r"(dst), "l"(src));
}
#define CP_COMMIT() asm volatile("cp.async.commit_group;" ::: "memory")
#define CP_WAIT0()  asm volatile("cp.async.wait_group 0;" ::: "memory")

// w-gen for 8 neighbors: packed fp16 weights + row-partial sums
struct W8 { uint4 v; float ssum; float cnt; };
__device__ __forceinline__ W8 wgen8(
    int4 a0, int4 a1, float4 p0, float4 p1, float4 q0, float4 q1,
    float P1r, float Q1r)
{
    int   av[8] = {a0.x, a0.y, a0.z, a0.w, a1.x, a1.y, a1.z, a1.w};
    float pv[8] = {p0.x, p0.y, p0.z, p0.w, p1.x, p1.y, p1.z, p1.w};
    float qv[8] = {q0.x, q0.y, q0.z, q0.w, q1.x, q1.y, q1.z, q1.w};
    unsigned short us[8];
    W8 r; r.ssum = 0.f; r.cnt = 0.f;
#pragma unroll
    for (int q = 0; q < 8; ++q) {
        float w = fmaxf(P1r * pv[q], Q1r * qv[q]);
        __half hw = __float2half_rn(w);
        bool on = av[q] > 0;
        us[q] = on ? __half_as_ushort(hw) : (unsigned short)0;
        if (on) { r.ssum += __half2float(hw); r.cnt += 1.f; }
    }
    r.v.x = (uint32_t)us[0] | ((uint32_t)us[1] << 16);
    r.v.y = (uint32_t)us[2] | ((uint32_t)us[3] << 16);
    r.v.z = (uint32_t)us[4] | ((uint32_t)us[5] << 16);
    r.v.w = (uint32_t)us[6] | ((uint32_t)us[7] << 16);
    return r;
}

// ---------------------------------------------------------------------------
// Merged tensor-core GEMM for both inputs.
// 2-pass split: h = x_hi*W_hi + x_hi*W_lo  (x_lo pass dropped; ~1.5e-4 h err)
// ---------------------------------------------------------------------------
__global__ __launch_bounds__(256) void gemm_all(
    const float* __restrict__ x0, const float* __restrict__ x1,
    const float* __restrict__ W0, const float* __restrict__ W1)
{
    __shared__ __align__(16) __half sAhi[128 * 40];
    __shared__ __align__(16) __half sWhi[32 * 136];
    __shared__ __align__(16) __half sWlo[32 * 136];

    const int bx = blockIdx.x;
    const float* A; const float* W; __half* Chi; __half* Clo; int K, mblk;
    if (bx < BATCH * N1 / 128) {
        A = x0; W = W0; K = F0K; mblk = bx;
        Chi = g_h0hi; Clo = g_h0lo;
    } else {
        A = x1; W = W1; K = F1K; mblk = bx - BATCH * N1 / 128;
        Chi = g_h1hi; Clo = g_h1lo;
    }

    const int t    = threadIdx.x;
    const int lane = t & 31;
    const int wid  = t >> 5;
    const int m0   = mblk * 128;
    const int nc0  = blockIdx.y * 128;

    const int ar = t >> 1;
    const int ac = (t & 1) * 16;
    const float* Ap = A + (size_t)(m0 + ar) * K + ac;
    const int wk = t >> 3;
    const int wc = (t & 7) * 16;
    const float* Wp = W + (size_t)wk * 256 + nc0 + wc;

    const int am0 = (wid & 3) * 32;
    const int cn0 = (wid >> 2) * 64;

    float cf[16][4];
#pragma unroll
    for (int i = 0; i < 16; ++i)
#pragma unroll
        for (int j = 0; j < 4; ++j) cf[i][j] = 0.f;

    float4 avr[4], wvr[4];
#pragma unroll
    for (int j = 0; j < 4; ++j) {
        avr[j] = *(const float4*)(Ap + j * 4);
        wvr[j] = *(const float4*)(Wp + j * 4);
    }

    for (int k0 = 0; k0 < K; k0 += 32) {
#pragma unroll
        for (int j = 0; j < 4; ++j) {
            float4 v = avr[j];
            __half2 h0 = __floats2half2_rn(v.x, v.y);
            __half2 h1 = __floats2half2_rn(v.z, v.w);
            int off = ar * 40 + ac + j * 4;
            *(__half2*)&sAhi[off]     = h0;
            *(__half2*)&sAhi[off + 2] = h1;
            v = wvr[j];
            h0 = __floats2half2_rn(v.x, v.y);
            h1 = __floats2half2_rn(v.z, v.w);
            __half2 l0 = __floats2half2_rn(v.x - __low2float(h0), v.y - __high2float(h0));
            __half2 l1 = __floats2half2_rn(v.z - __low2float(h1), v.w - __high2float(h1));
            off = wk * 136 + wc + j * 4;
            *(__half2*)&sWhi[off]     = h0;
            *(__half2*)&sWhi[off + 2] = h1;
            *(__half2*)&sWlo[off]     = l0;
            *(__half2*)&sWlo[off + 2] = l1;
        }
        __syncthreads();

        if (k0 + 32 < K) {
#pragma unroll
            for (int j = 0; j < 4; ++j) {
                avr[j] = *(const float4*)(Ap + k0 + 32 + j * 4);
                wvr[j] = *(const float4*)(Wp + (size_t)(k0 + 32) * 256 + j * 4);
            }
        }

#pragma unroll
        for (int kk = 0; kk < 2; ++kk) {
            uint32_t ah[2][4];
#pragma unroll
            for (int mt = 0; mt < 2; ++mt) {
                const int arow = am0 + mt * 16 + (lane & 15);
                const int acol = kk * 16 + (lane >> 4) * 8;
                ldsm4(ah[mt], &sAhi[arow * 40 + acol]);
            }
#pragma unroll
            for (int nt = 0; nt < 4; ++nt) {
                uint32_t bh[4], bl[4];
                const int boff = (kk * 16 + (lane & 15)) * 136 + cn0 +
                                 nt * 16 + (lane >> 4) * 8;
                ldsm4t(bh, &sWhi[boff]);
                ldsm4t(bl, &sWlo[boff]);
#pragma unroll
                for (int mt = 0; mt < 2; ++mt) {
                    float* c0 = cf[mt * 8 + nt * 2];
                    float* c1 = cf[mt * 8 + nt * 2 + 1];
                    mma16816(c0, ah[mt], bh[0], bh[1]);
                    mma16816(c1, ah[mt], bh[2], bh[3]);
                    mma16816(c0, ah[mt], bl[0], bl[1]);
                    mma16816(c1, ah[mt], bl[2], bl[3]);
                }
            }
        }
        __syncthreads();
    }

    const int rlo = am0 + (lane >> 2);
#pragma unroll
    for (int mt = 0; mt < 2; ++mt) {
#pragma unroll
        for (int j = 0; j < 8; ++j) {
            int nt = j >> 1;
            int half8 = j & 1;
            float* cc = cf[mt * 8 + j];
            int row = rlo + mt * 16;
            int col = nc0 + cn0 + nt * 16 + half8 * 8 + (lane & 3) * 2;
            {
                float x = cc[0], y = cc[1];
                __half2 hi = __floats2half2_rn(x, y);
                __half2 lo = __floats2half2_rn(x - __low2float(hi), y - __high2float(hi));
                size_t off = (size_t)(m0 + row) * 256 + col;
                *(__half2*)&Chi[off] = hi;
                *(__half2*)&Clo[off] = lo;
            }
            {
                float x = cc[2], y = cc[3];
                __half2 hi = __floats2half2_rn(x, y);
                __half2 lo = __floats2half2_rn(x - __low2float(hi), y - __high2float(hi));
                size_t off = (size_t)(m0 + row + 8) * 256 + col;
                *(__half2*)&Chi[off] = hi;
                *(__half2*)&Clo[off] = lo;
            }
        }
    }
}

// ---------------------------------------------------------------------------
// Merged triple dot over both h tensors
// ---------------------------------------------------------------------------
__global__ __launch_bounds__(256) void edot_all(
    const float* __restrict__ a1_0, const float* __restrict__ a2_0,
    const float* __restrict__ a1_1, const float* __restrict__ a2_1)
{
    const int gr = blockIdx.x * 8 + (threadIdx.x >> 5);
    const int lane = threadIdx.x & 31;
    const __half *ph, *pl;
    const float *v0, *v1, *v2;
    float *e0, *e1, *e2;
    int r;
    if (gr < BATCH * N1) {
        r = gr;
        ph = g_h0hi + (size_t)r * 256; pl = g_h0lo + (size_t)r * 256;
        v0 = a1_0; v1 = a2_0; v2 = a2_1;
        e0 = g_eA; e1 = g_eB; e2 = g_eE;
    } else {
        r = gr - BATCH * N1;
        ph = g_h1hi + (size_t)r * 256; pl = g_h1lo + (size_t)r * 256;
        v0 = a2_0; v1 = a1_1; v2 = a2_1;
        e0 = g_eC; e1 = g_eD; e2 = g_eF;
    }
    float s0 = 0.f, s1 = 0.f, s2 = 0.f;
#pragma unroll
    for (int i = 0; i < 8; ++i) {
        int c = lane + i * 32;
        float x = __half2float(ph[c]) + __half2float(pl[c]);
        s0 += x * v0[c];
        s1 += x * v1[c];
        s2 += x * v2[c];
    }
#pragma unroll
    for (int o = 16; o > 0; o >>= 1) {
        s0 += __shfl_xor_sync(0xffffffffu, s0, o);
        s1 += __shfl_xor_sync(0xffffffffu, s1, o);
        s2 += __shfl_xor_sync(0xffffffffu, s2, o);
    }
    if (lane == 0) { e0[r] = s0; e1[r] = s1; e2[r] = s2; }
}

// ---------------------------------------------------------------------------
// Merged per-batch max + P2/Q2 generation (one block per (blk, batch))
// ---------------------------------------------------------------------------
__global__ __launch_bounds__(256) void pqmax_all()
{
    __shared__ float red[256];
    const int blk = blockIdx.x >> 6;
    const int b   = blockIdx.x & 63;
    const int t   = threadIdx.x;
    const float* p; int M; size_t off;
    if (blk == 0)      { p = g_eB; M = N1; off = PQ_O0; }
    else if (blk == 1) { p = g_eC; M = N2; off = PQ_O1; }
    else if (blk == 2) { p = g_eE; M = N1; off = PQ_O2; }
    else               { p = g_eF; M = N2; off = PQ_O3; }
    p += (size_t)b * M;
    float m = -3.4e38f;
    for (int i = t; i < M; i += 256) m = fmaxf(m, p[i]);
    red[t] = m;
    __syncthreads();
    for (int s = 128; s > 0; s >>= 1) {
        if (t < s) red[t] = fmaxf(red[t], red[t + s]);
        __syncthreads();
    }
    const float mx = red[0];
    if (t == 0) g_mx[blk * BATCH + b] = mx;
    float* P = g_P2 + off + (size_t)b * M;
    float* Q = g_Q2 + off + (size_t)b * M;
    for (int i = t; i < M; i += 256) {
        float d = p[i] - mx;
        P[i] = __expf(d);
        Q[i] = __expf(0.2f * d);
    }
}

// ---------------------------------------------------------------------------
// Merged fused masked attention, 2-stage ping-pong (STATIC smem: 2 CTAs/SM).
// Warp mapping: 2 m-groups x 4 n-groups.  (bit-identical to R11)
// ---------------------------------------------------------------------------
__global__ __launch_bounds__(256, 2) void att_all(
    const int* __restrict__ adj00, const int* __restrict__ adj01,
    const int* __restrict__ adj10, const int* __restrict__ adj11,
    const float* __restrict__ bias, float* __restrict__ out)
{
    __shared__ __align__(16) __half sW[2][64 * 40];
    __shared__ __align__(16) __half sB[2][32 * 264];
    __shared__ float sP1[64], sQ1[64], sSum[64], sDeg[64];

    const int bx = blockIdx.x;   // 16 blk00 | 8 blk10 | 16 blk01 | 8 blk11
    const int b  = blockIdx.y;
    const __half* g; const int* adjB; const float* e1B;
    int mxi, N, M, tl; size_t pqo, oof;
    if (bx < 16) {
        tl = bx;      g = g_h0hi; adjB = adj00; e1B = g_eA; mxi = 0;
        pqo = PQ_O0; oof = OO_00; N = N1; M = N1;
    } else if (bx < 24) {
        tl = bx - 16; g = g_h0hi; adjB = adj10; e1B = g_eD; mxi = 2;
        pqo = PQ_O2; oof = OO_10; N = N2; M = N1;
    } else if (bx < 40) {
        tl = bx - 24; g = g_h1hi; adjB = adj01; e1B = g_eA; mxi = 1;
        pqo = PQ_O1; oof = OO_01; N = N1; M = N2;
    } else {
        tl = bx - 40; g = g_h1hi; adjB = adj11; e1B = g_eD; mxi = 3;
        pqo = PQ_O3; oof = OO_11; N = N2; M = N2;
    }
    const int n0 = tl * 64;

    const int t    = threadIdx.x;
    const int lane = t & 31;
    const int wid  = t >> 5;

    if (t < 64) {
        float v = e1B[(size_t)b * N + n0 + t] + g_mx[mxi * BATCH + b];
        float sh = fmaxf(v, 0.2f * v);
        sP1[t] = __expf(v - sh);
        sQ1[t] = __expf(0.2f * v - sh);
        sSum[t] = 0.f;
        sDeg[t] = 0.f;
    }
    __syncthreads();

    float c[16][4];
#pragma unroll
    for (int i = 0; i < 16; ++i)
#pragma unroll
        for (int j = 0; j < 4; ++j) c[i][j] = 0.f;

    // g tile cp.async: row k = t>>3, cols (t&7)*32 .. +31
    const int bk = t >> 3;
    const int bc = (t & 7) * 32;
    const __half* gsrc = g + ((size_t)b * M + bk) * 256 + bc;
    const uint32_t sb0 = (uint32_t)__cvta_generic_to_shared(&sB[0][bk * 264 + bc]);
    const uint32_t sb1 = (uint32_t)__cvta_generic_to_shared(&sB[1][bk * 264 + bc]);

    // w-gen: row r = t>>2, cols (t&3)*8 .. +7
    const int wr = t >> 2;
    const int wc = (t & 3) * 8;
    const int* adjp = adjB + ((size_t)b * N + n0 + wr) * M + wc;
    const float* p2p = g_P2 + pqo + (size_t)b * M + wc;
    const float* q2p = g_Q2 + pqo + (size_t)b * M + wc;
    const float P1r = sP1[wr];
    const float Q1r = sQ1[wr];

    // MMA mapping: warp = (wid&1) m-group (32 rows) x (wid>>1) n-group (64 cols)
    const int mgrp = (wid & 1) * 32;
    const int ngrp = (wid >> 1) * 64;
    const int aOff0 = (mgrp + (lane & 15)) * 40 + (lane >> 4) * 8;
    const int aOff1 = aOff0 + 16 * 40;
    const int bRowOff = (lane & 15) * 264 + ngrp + (lane >> 4) * 8;

    const int iters = M >> 5;

    // ---- prolog: stage chunk 0 ----
    {
#pragma unroll
        for (int j = 0; j < 4; ++j) cp16(sb0 + j * 16, gsrc + j * 8);
        CP_COMMIT();
        int4 a0 = *(const int4*)(adjp);
        int4 a1 = *(const int4*)(adjp + 4);
        float4 p0 = *(const float4*)(p2p);
        float4 p1 = *(const float4*)(p2p + 4);
        float4 q0 = *(const float4*)(q2p);
        float4 q1 = *(const float4*)(q2p + 4);
        W8 w = wgen8(a0, a1, p0, p1, q0, q1, P1r, Q1r);
        *(uint4*)&sW[0][wr * 40 + wc] = w.v;
        float ssum = w.ssum, cnt = w.cnt;
        ssum += __shfl_xor_sync(0xffffffffu, ssum, 1);
        ssum += __shfl_xor_sync(0xffffffffu, ssum, 2);
        cnt  += __shfl_xor_sync(0xffffffffu, cnt, 1);
        cnt  += __shfl_xor_sync(0xffffffffu, cnt, 2);
        if ((t & 3) == 0) { sSum[wr] += ssum; sDeg[wr] += cnt; }
        CP_WAIT0();
    }
    __syncthreads();

    for (int it = 0; it < iters; ++it) {
        const int cur = it & 1;
        const bool hasNext = (it + 1) < iters;
        int4 a0, a1; float4 p0, p1, q0, q1;

        if (hasNext) {
            const int m1 = (it + 1) * 32;
            const uint32_t sbn = (cur ^ 1) ? sb1 : sb0;
#pragma unroll
            for (int j = 0; j < 4; ++j)
                cp16(sbn + j * 16, gsrc + (size_t)m1 * 256 + j * 8);
            CP_COMMIT();
            a0 = *(const int4*)(adjp + m1);
            a1 = *(const int4*)(adjp + m1 + 4);
            p0 = *(const float4*)(p2p + m1);
            p1 = *(const float4*)(p2p + m1 + 4);
            q0 = *(const float4*)(q2p + m1);
            q1 = *(const float4*)(q2p + m1 + 4);
        }

        // ---- MMA from buffer cur: 2 m-tiles share each B fragment ----
        {
            const __half* wbase = &sW[cur][0];
            const __half* bbase = &sB[cur][0];
#pragma unroll
            for (int kk = 0; kk < 2; ++kk) {
                uint32_t af0[4], af1[4];
                ldsm4(af0, wbase + aOff0 + kk * 16);
                ldsm4(af1, wbase + aOff1 + kk * 16);
#pragma unroll
                for (int nb = 0; nb < 4; ++nb) {
                    uint32_t bh[4];
                    ldsm4t(bh, bbase + kk * 16 * 264 + bRowOff + nb * 16);
                    mma16816(c[nb * 2],     af0, bh[0], bh[1]);
                    mma16816(c[nb * 2 + 1], af0, bh[2], bh[3]);
                    mma16816(c[8 + nb * 2],     af1, bh[0], bh[1]);
                    mma16816(c[8 + nb * 2 + 1], af1, bh[2], bh[3]);
                }
            }
        }

        if (hasNext) {
            W8 w = wgen8(a0, a1, p0, p1, q0, q1, P1r, Q1r);
            *(uint4*)&sW[cur ^ 1][wr * 40 + wc] = w.v;
            float ssum = w.ssum, cnt = w.cnt;
            ssum += __shfl_xor_sync(0xffffffffu, ssum, 1);
            ssum += __shfl_xor_sync(0xffffffffu, ssum, 2);
            cnt  += __shfl_xor_sync(0xffffffffu, cnt, 1);
            cnt  += __shfl_xor_sync(0xffffffffu, cnt, 2);
            if ((t & 3) == 0) { sSum[wr] += ssum; sDeg[wr] += cnt; }
            CP_WAIT0();
        }
        __syncthreads();
    }

    // ---- epilogue ----
    float* ob = out + oof;
#pragma unroll
    for (int mt = 0; mt < 2; ++mt) {
        const int rlo = mgrp + mt * 16 + (lane >> 2);
        const int rhi = rlo + 8;
        float slo = (sDeg[rlo] > 0.f && sSum[rlo] > 0.f) ? sDeg[rlo] / sSum[rlo] : 0.f;
        float shi = (sDeg[rhi] > 0.f && sSum[rhi] > 0.f) ? sDeg[rhi] / sSum[rhi] : 0.f;
        float* olo = ob + ((size_t)b * N + n0 + rlo) * 256;
        float* ohi = ob + ((size_t)b * N + n0 + rhi) * 256;
#pragma unroll
        for (int j = 0; j < 8; ++j) {
            int nt = j >> 1;
            int half8 = j & 1;
            float* cc = c[mt * 8 + j];
            int col = ngrp + nt * 16 + half8 * 8 + (lane & 3) * 2;
            float b0 = bias[col], b1 = bias[col + 1];
            float2 v0 = make_float2(cc[0] * slo + b0, cc[1] * slo + b1);
            float2 v1 = make_float2(cc[2] * shi + b0, cc[3] * shi + b1);
            *(float2*)(olo + col) = v0;
            *(float2*)(ohi + col) = v1;
        }
    }
}

// ---------------------------------------------------------------------------
// Launch: 4 kernels total
// ---------------------------------------------------------------------------
extern "C" void kernel_launch(void* const* d_in, const int* in_sizes, int n_in,
                              void* d_out, int out_size)
{
    const float* x0   = (const float*)d_in[0];
    const float* x1   = (const float*)d_in[1];
    const float* W0   = (const float*)d_in[2];
    const float* W1   = (const float*)d_in[3];
    const float* a1_0 = (const float*)d_in[4];
    const float* a2_0 = (const float*)d_in[5];
    const float* a1_1 = (const float*)d_in[6];
    const float* a2_1 = (const float*)d_in[7];
    const float* bias = (const float*)d_in[8];
    const int* adj00  = (const int*)d_in[9];
    const int* adj01  = (const int*)d_in[10];
    const int* adj10  = (const int*)d_in[11];
    const int* adj11  = (const int*)d_in[12];
    float* out = (float*)d_out;

    const int R0 = BATCH * N1;   // 65536
    const int R1 = BATCH * N2;   // 32768

    gemm_all<<<dim3((R0 + R1) / 128, 2), 256>>>(x0, x1, W0, W1);
    edot_all<<<(R0 + R1) / 8, 256>>>(a1_0, a2_0, a1_1, a2_1);
    pqmax_all<<<4 * BATCH, 256>>>();
    att_all<<<dim3(48, BATCH), 256>>>(adj00, adj01, adj10, adj11, bias, out);
}

// round 13
// speedup vs baseline: 1.1901x; 1.1901x over previous
#include <cuda_runtime.h>
#include <cuda_fp16.h>
#include <cstdint>
#include <cstddef>

#define BATCH 64
#define N1 1024
#define N2 512
#define F0K 512
#define F1K 384

// ---------------------------------------------------------------------------
// Scratch
// ---------------------------------------------------------------------------
__device__ __half g_h0hi[(size_t)BATCH * N1 * 256];
__device__ __half g_h0lo[(size_t)BATCH * N1 * 256];
__device__ __half g_h1hi[(size_t)BATCH * N2 * 256];
__device__ __half g_h1lo[(size_t)BATCH * N2 * 256];
__device__ float g_eA[BATCH * N1];
__device__ float g_eB[BATCH * N1];
__device__ float g_eC[BATCH * N2];
__device__ float g_eD[BATCH * N2];
__device__ float g_eE[BATCH * N1];
__device__ float g_eF[BATCH * N2];
__device__ float g_mx[4 * BATCH];
__device__ float g_P2[2 * BATCH * (N1 + N2)];
__device__ float g_Q2[2 * BATCH * (N1 + N2)];

// P2/Q2 segment offsets
#define PQ_O0 ((size_t)0)
#define PQ_O1 ((size_t)BATCH * N1)
#define PQ_O2 (PQ_O1 + (size_t)BATCH * N2)
#define PQ_O3 (PQ_O2 + (size_t)BATCH * N1)
// output segment offsets
#define OO_00 ((size_t)0)
#define OO_01 ((size_t)BATCH * N1 * 256)
#define OO_10 (OO_01 + (size_t)BATCH * N1 * 256)
#define OO_11 (OO_10 + (size_t)BATCH * N2 * 256)

// ---------------------------------------------------------------------------
// mma.sync / ldmatrix / cp.async helpers (sm_80 PTX, valid at base sm_103)
// ---------------------------------------------------------------------------
__device__ __forceinline__ void ldsm4(uint32_t* d, const void* p) {
    uint32_t a = (uint32_t)__cvta_generic_to_shared(p);
    asm volatile("ldmatrix.sync.aligned.m8n8.x4.shared.b16 {%0,%1,%2,%3}, [%4];"
                 : "=r"(d[0]), "=r"(d[1]), "=r"(d[2]), "=r"(d[3]) : "r"(a));
}
__device__ __forceinline__ void ldsm4t(uint32_t* d, const void* p) {
    uint32_t a = (uint32_t)__cvta_generic_to_shared(p);
    asm volatile("ldmatrix.sync.aligned.m8n8.x4.trans.shared.b16 {%0,%1,%2,%3}, [%4];"
                 : "=r"(d[0]), "=r"(d[1]), "=r"(d[2]), "=r"(d[3]) : "r"(a));
}
__device__ __forceinline__ void mma16816(float* c, const uint32_t* a,
                                         uint32_t b0, uint32_t b1) {
    asm volatile(
        "mma.sync.aligned.m16n8k16.row.col.f32.f16.f16.f32 "
        "{%0,%1,%2,%3}, {%4,%5,%6,%7}, {%8,%9}, {%0,%1,%2,%3};"
        : "+f"(c[0]), "+f"(c[1]), "+f"(c[2]), "+f"(c[3])
        : "r"(a[0]), "r"(a[1]), "r"(a[2]), "r"(a[3]), "r"(b0), "r"(b1));
}
__device__ __forceinline__ void cp16(uint32_t dst, const void* src) {
    asm volatile("cp.async.cg.shared.global [%0], [%1], 16;"
                 :: "r"(dst), "l"(src));
}
#define CP_COMMIT() asm volatile("cp.async.commit_group;" ::: "memory")
#define CP_WAIT0()  asm volatile("cp.async.wait_group 0;" ::: "memory")

// w-gen for 8 neighbors: packed fp16 weights + row-partial sums
struct W8 { uint4 v; float ssum; float cnt; };
__device__ __forceinline__ W8 wgen8(
    int4 a0, int4 a1, float4 p0, float4 p1, float4 q0, float4 q1,
    float P1r, float Q1r)
{
    int   av[8] = {a0.x, a0.y, a0.z, a0.w, a1.x, a1.y, a1.z, a1.w};
    float pv[8] = {p0.x, p0.y, p0.z, p0.w, p1.x, p1.y, p1.z, p1.w};
    float qv[8] = {q0.x, q0.y, q0.z, q0.w, q1.x, q1.y, q1.z, q1.w};
    unsigned short us[8];
    W8 r; r.ssum = 0.f; r.cnt = 0.f;
#pragma unroll
    for (int q = 0; q < 8; ++q) {
        float w = fmaxf(P1r * pv[q], Q1r * qv[q]);
        __half hw = __float2half_rn(w);
        bool on = av[q] > 0;
        us[q] = on ? __half_as_ushort(hw) : (unsigned short)0;
        if (on) { r.ssum += __half2float(hw); r.cnt += 1.f; }
    }
    r.v.x = (uint32_t)us[0] | ((uint32_t)us[1] << 16);
    r.v.y = (uint32_t)us[2] | ((uint32_t)us[3] << 16);
    r.v.z = (uint32_t)us[4] | ((uint32_t)us[5] << 16);
    r.v.w = (uint32_t)us[6] | ((uint32_t)us[7] << 16);
    return r;
}

// ---------------------------------------------------------------------------
// Merged tensor-core GEMM for both inputs (R11 3-pass version).
// ---------------------------------------------------------------------------
__global__ __launch_bounds__(256) void gemm_all(
    const float* __restrict__ x0, const float* __restrict__ x1,
    const float* __restrict__ W0, const float* __restrict__ W1)
{
    __shared__ __align__(16) __half sAhi[128 * 40];
    __shared__ __align__(16) __half sAlo[128 * 40];
    __shared__ __align__(16) __half sWhi[32 * 136];
    __shared__ __align__(16) __half sWlo[32 * 136];

    const int bx = blockIdx.x;
    const float* A; const float* W; __half* Chi; __half* Clo; int K, mblk;
    if (bx < BATCH * N1 / 128) {
        A = x0; W = W0; K = F0K; mblk = bx;
        Chi = g_h0hi; Clo = g_h0lo;
    } else {
        A = x1; W = W1; K = F1K; mblk = bx - BATCH * N1 / 128;
        Chi = g_h1hi; Clo = g_h1lo;
    }

    const int t    = threadIdx.x;
    const int lane = t & 31;
    const int wid  = t >> 5;
    const int m0   = mblk * 128;
    const int nc0  = blockIdx.y * 128;

    const int ar = t >> 1;
    const int ac = (t & 1) * 16;
    const float* Ap = A + (size_t)(m0 + ar) * K + ac;
    const int wk = t >> 3;
    const int wc = (t & 7) * 16;
    const float* Wp = W + (size_t)wk * 256 + nc0 + wc;

    const int am0 = (wid & 3) * 32;
    const int cn0 = (wid >> 2) * 64;

    float cf[16][4];
#pragma unroll
    for (int i = 0; i < 16; ++i)
#pragma unroll
        for (int j = 0; j < 4; ++j) cf[i][j] = 0.f;

    float4 avr[4], wvr[4];
#pragma unroll
    for (int j = 0; j < 4; ++j) {
        avr[j] = *(const float4*)(Ap + j * 4);
        wvr[j] = *(const float4*)(Wp + j * 4);
    }

    for (int k0 = 0; k0 < K; k0 += 32) {
#pragma unroll
        for (int j = 0; j < 4; ++j) {
            float4 v = avr[j];
            __half2 h0 = __floats2half2_rn(v.x, v.y);
            __half2 h1 = __floats2half2_rn(v.z, v.w);
            __half2 l0 = __floats2half2_rn(v.x - __low2float(h0), v.y - __high2float(h0));
            __half2 l1 = __floats2half2_rn(v.z - __low2float(h1), v.w - __high2float(h1));
            int off = ar * 40 + ac + j * 4;
            *(__half2*)&sAhi[off]     = h0;
            *(__half2*)&sAhi[off + 2] = h1;
            *(__half2*)&sAlo[off]     = l0;
            *(__half2*)&sAlo[off + 2] = l1;
            v = wvr[j];
            h0 = __floats2half2_rn(v.x, v.y);
            h1 = __floats2half2_rn(v.z, v.w);
            l0 = __floats2half2_rn(v.x - __low2float(h0), v.y - __high2float(h0));
            l1 = __floats2half2_rn(v.z - __low2float(h1), v.w - __high2float(h1));
            off = wk * 136 + wc + j * 4;
            *(__half2*)&sWhi[off]     = h0;
            *(__half2*)&sWhi[off + 2] = h1;
            *(__half2*)&sWlo[off]     = l0;
            *(__half2*)&sWlo[off + 2] = l1;
        }
        __syncthreads();

        if (k0 + 32 < K) {
#pragma unroll
            for (int j = 0; j < 4; ++j) {
                avr[j] = *(const float4*)(Ap + k0 + 32 + j * 4);
                wvr[j] = *(const float4*)(Wp + (size_t)(k0 + 32) * 256 + j * 4);
            }
        }

#pragma unroll
        for (int kk = 0; kk < 2; ++kk) {
            uint32_t ah[2][4], al[2][4];
#pragma unroll
            for (int mt = 0; mt < 2; ++mt) {
                const int arow = am0 + mt * 16 + (lane & 15);
                const int acol = kk * 16 + (lane >> 4) * 8;
                ldsm4(ah[mt], &sAhi[arow * 40 + acol]);
                ldsm4(al[mt], &sAlo[arow * 40 + acol]);
            }
#pragma unroll
            for (int nt = 0; nt < 4; ++nt) {
                uint32_t bh[4], bl[4];
                const int boff = (kk * 16 + (lane & 15)) * 136 + cn0 +
                                 nt * 16 + (lane >> 4) * 8;
                ldsm4t(bh, &sWhi[boff]);
                ldsm4t(bl, &sWlo[boff]);
#pragma unroll
                for (int mt = 0; mt < 2; ++mt) {
                    float* c0 = cf[mt * 8 + nt * 2];
                    float* c1 = cf[mt * 8 + nt * 2 + 1];
                    mma16816(c0, ah[mt], bh[0], bh[1]);
                    mma16816(c1, ah[mt], bh[2], bh[3]);
                    mma16816(c0, ah[mt], bl[0], bl[1]);
                    mma16816(c1, ah[mt], bl[2], bl[3]);
                    mma16816(c0, al[mt], bh[0], bh[1]);
                    mma16816(c1, al[mt], bh[2], bh[3]);
                }
            }
        }
        __syncthreads();
    }

    const int rlo = am0 + (lane >> 2);
#pragma unroll
    for (int mt = 0; mt < 2; ++mt) {
#pragma unroll
        for (int j = 0; j < 8; ++j) {
            int nt = j >> 1;
            int half8 = j & 1;
            float* cc = cf[mt * 8 + j];
            int row = rlo + mt * 16;
            int col = nc0 + cn0 + nt * 16 + half8 * 8 + (lane & 3) * 2;
            {
                float x = cc[0], y = cc[1];
                __half2 hi = __floats2half2_rn(x, y);
                __half2 lo = __floats2half2_rn(x - __low2float(hi), y - __high2float(hi));
                size_t off = (size_t)(m0 + row) * 256 + col;
                *(__half2*)&Chi[off] = hi;
                *(__half2*)&Clo[off] = lo;
            }
            {
                float x = cc[2], y = cc[3];
                __half2 hi = __floats2half2_rn(x, y);
                __half2 lo = __floats2half2_rn(x - __low2float(hi), y - __high2float(hi));
                size_t off = (size_t)(m0 + row + 8) * 256 + col;
                *(__half2*)&Chi[off] = hi;
                *(__half2*)&Clo[off] = lo;
            }
        }
    }
}

// ---------------------------------------------------------------------------
// Merged triple dot over both h tensors
// ---------------------------------------------------------------------------
__global__ __launch_bounds__(256) void edot_all(
    const float* __restrict__ a1_0, const float* __restrict__ a2_0,
    const float* __restrict__ a1_1, const float* __restrict__ a2_1)
{
    const int gr = blockIdx.x * 8 + (threadIdx.x >> 5);
    const int lane = threadIdx.x & 31;
    const __half *ph, *pl;
    const float *v0, *v1, *v2;
    float *e0, *e1, *e2;
    int r;
    if (gr < BATCH * N1) {
        r = gr;
        ph = g_h0hi + (size_t)r * 256; pl = g_h0lo + (size_t)r * 256;
        v0 = a1_0; v1 = a2_0; v2 = a2_1;
        e0 = g_eA; e1 = g_eB; e2 = g_eE;
    } else {
        r = gr - BATCH * N1;
        ph = g_h1hi + (size_t)r * 256; pl = g_h1lo + (size_t)r * 256;
        v0 = a2_0; v1 = a1_1; v2 = a2_1;
        e0 = g_eC; e1 = g_eD; e2 = g_eF;
    }
    float s0 = 0.f, s1 = 0.f, s2 = 0.f;
#pragma unroll
    for (int i = 0; i < 8; ++i) {
        int c = lane + i * 32;
        float x = __half2float(ph[c]) + __half2float(pl[c]);
        s0 += x * v0[c];
        s1 += x * v1[c];
        s2 += x * v2[c];
    }
#pragma unroll
    for (int o = 16; o > 0; o >>= 1) {
        s0 += __shfl_xor_sync(0xffffffffu, s0, o);
        s1 += __shfl_xor_sync(0xffffffffu, s1, o);
        s2 += __shfl_xor_sync(0xffffffffu, s2, o);
    }
    if (lane == 0) { e0[r] = s0; e1[r] = s1; e2[r] = s2; }
}

// ---------------------------------------------------------------------------
// Merged per-batch max + P2/Q2 generation (one block per (blk, batch))
// ---------------------------------------------------------------------------
__global__ __launch_bounds__(256) void pqmax_all()
{
    __shared__ float red[256];
    const int blk = blockIdx.x >> 6;
    const int b   = blockIdx.x & 63;
    const int t   = threadIdx.x;
    const float* p; int M; size_t off;
    if (blk == 0)      { p = g_eB; M = N1; off = PQ_O0; }
    else if (blk == 1) { p = g_eC; M = N2; off = PQ_O1; }
    else if (blk == 2) { p = g_eE; M = N1; off = PQ_O2; }
    else               { p = g_eF; M = N2; off = PQ_O3; }
    p += (size_t)b * M;
    float m = -3.4e38f;
    for (int i = t; i < M; i += 256) m = fmaxf(m, p[i]);
    red[t] = m;
    __syncthreads();
    for (int s = 128; s > 0; s >>= 1) {
        if (t < s) red[t] = fmaxf(red[t], red[t + s]);
        __syncthreads();
    }
    const float mx = red[0];
    if (t == 0) g_mx[blk * BATCH + b] = mx;
    float* P = g_P2 + off + (size_t)b * M;
    float* Q = g_Q2 + off + (size_t)b * M;
    for (int i = t; i < M; i += 256) {
        float d = p[i] - mx;
        P[i] = __expf(d);
        Q[i] = __expf(0.2f * d);
    }
}

// ---------------------------------------------------------------------------
// Merged fused masked attention, 2-stage ping-pong.
// 128-row CTAs, 512 threads (16 warps, 4m x 4n warp map), 1 CTA/SM.
// Halves g traffic + per-MMA barrier overhead vs 64-row CTAs.
// ---------------------------------------------------------------------------
__global__ __launch_bounds__(512, 1) void att_all(
    const int* __restrict__ adj00, const int* __restrict__ adj01,
    const int* __restrict__ adj10, const int* __restrict__ adj11,
    const float* __restrict__ bias, float* __restrict__ out)
{
    __shared__ __align__(16) __half sW[2][128 * 40];   // 20480 B
    __shared__ __align__(16) __half sB[2][32 * 264];   // 33792 B
    __shared__ float sP1[128], sQ1[128], sSum[128], sDeg[128];

    const int bx = blockIdx.x;   // 8 blk00 | 4 blk10 | 8 blk01 | 4 blk11
    const int b  = blockIdx.y;
    const __half* g; const int* adjB; const float* e1B;
    int mxi, N, M, tl; size_t pqo, oof;
    if (bx < 8) {
        tl = bx;      g = g_h0hi; adjB = adj00; e1B = g_eA; mxi = 0;
        pqo = PQ_O0; oof = OO_00; N = N1; M = N1;
    } else if (bx < 12) {
        tl = bx - 8;  g = g_h0hi; adjB = adj10; e1B = g_eD; mxi = 2;
        pqo = PQ_O2; oof = OO_10; N = N2; M = N1;
    } else if (bx < 20) {
        tl = bx - 12; g = g_h1hi; adjB = adj01; e1B = g_eA; mxi = 1;
        pqo = PQ_O1; oof = OO_01; N = N1; M = N2;
    } else {
        tl = bx - 20; g = g_h1hi; adjB = adj11; e1B = g_eD; mxi = 3;
        pqo = PQ_O3; oof = OO_11; N = N2; M = N2;
    }
    const int n0 = tl * 128;

    const int t    = threadIdx.x;
    const int lane = t & 31;
    const int wid  = t >> 5;

    if (t < 128) {
        float v = e1B[(size_t)b * N + n0 + t] + g_mx[mxi * BATCH + b];
        float sh = fmaxf(v, 0.2f * v);
        sP1[t] = __expf(v - sh);
        sQ1[t] = __expf(0.2f * v - sh);
        sSum[t] = 0.f;
        sDeg[t] = 0.f;
    }
    __syncthreads();

    float c[16][4];
#pragma unroll
    for (int i = 0; i < 16; ++i)
#pragma unroll
        for (int j = 0; j < 4; ++j) c[i][j] = 0.f;

    // g tile cp.async: row k = t>>4 (32 rows), cols (t&15)*16 .. +15 (2x16B)
    const int bk = t >> 4;
    const int bc = (t & 15) * 16;
    const __half* gsrc = g + ((size_t)b * M + bk) * 256 + bc;
    const uint32_t sb0 = (uint32_t)__cvta_generic_to_shared(&sB[0][bk * 264 + bc]);
    const uint32_t sb1 = (uint32_t)__cvta_generic_to_shared(&sB[1][bk * 264 + bc]);

    // w-gen: row r = t>>2 (0..127), cols (t&3)*8 .. +7
    const int wr = t >> 2;
    const int wc = (t & 3) * 8;
    const int* adjp = adjB + ((size_t)b * N + n0 + wr) * M + wc;
    const float* p2p = g_P2 + pqo + (size_t)b * M + wc;
    const float* q2p = g_Q2 + pqo + (size_t)b * M + wc;
    const float P1r = sP1[wr];
    const float Q1r = sQ1[wr];

    // MMA mapping: warp = (wid&3) m-group (32 rows) x (wid>>2) n-group (64 cols)
    const int mgrp = (wid & 3) * 32;
    const int ngrp = (wid >> 2) * 64;
    const int aOff0 = (mgrp + (lane & 15)) * 40 + (lane >> 4) * 8;
    const int aOff1 = aOff0 + 16 * 40;
    const int bRowOff = (lane & 15) * 264 + ngrp + (lane >> 4) * 8;

    const int iters = M >> 5;

    // ---- prolog: stage chunk 0 ----
    {
#pragma unroll
        for (int j = 0; j < 2; ++j) cp16(sb0 + j * 16, gsrc + j * 8);
        CP_COMMIT();
        int4 a0 = *(const int4*)(adjp);
        int4 a1 = *(const int4*)(adjp + 4);
        float4 p0 = *(const float4*)(p2p);
        float4 p1 = *(const float4*)(p2p + 4);
        float4 q0 = *(const float4*)(q2p);
        float4 q1 = *(const float4*)(q2p + 4);
        W8 w = wgen8(a0, a1, p0, p1, q0, q1, P1r, Q1r);
        *(uint4*)&sW[0][wr * 40 + wc] = w.v;
        float ssum = w.ssum, cnt = w.cnt;
        ssum += __shfl_xor_sync(0xffffffffu, ssum, 1);
        ssum += __shfl_xor_sync(0xffffffffu, ssum, 2);
        cnt  += __shfl_xor_sync(0xffffffffu, cnt, 1);
        cnt  += __shfl_xor_sync(0xffffffffu, cnt, 2);
        if ((t & 3) == 0) { sSum[wr] += ssum; sDeg[wr] += cnt; }
        CP_WAIT0();
    }
    __syncthreads();

    for (int it = 0; it < iters; ++it) {
        const int cur = it & 1;
        const bool hasNext = (it + 1) < iters;
        int4 a0, a1; float4 p0, p1, q0, q1;

        if (hasNext) {
            const int m1 = (it + 1) * 32;
            const uint32_t sbn = (cur ^ 1) ? sb1 : sb0;
#pragma unroll
            for (int j = 0; j < 2; ++j)
                cp16(sbn + j * 16, gsrc + (size_t)m1 * 256 + j * 8);
            CP_COMMIT();
            a0 = *(const int4*)(adjp + m1);
            a1 = *(const int4*)(adjp + m1 + 4);
            p0 = *(const float4*)(p2p + m1);
            p1 = *(const float4*)(p2p + m1 + 4);
            q0 = *(const float4*)(q2p + m1);
            q1 = *(const float4*)(q2p + m1 + 4);
        }

        // ---- MMA from buffer cur: 2 m-tiles share each B fragment ----
        {
            const __half* wbase = &sW[cur][0];
            const __half* bbase = &sB[cur][0];
#pragma unroll
            for (int kk = 0; kk < 2; ++kk) {
                uint32_t af0[4], af1[4];
                ldsm4(af0, wbase + aOff0 + kk * 16);
                ldsm4(af1, wbase + aOff1 + kk * 16);
#pragma unroll
                for (int nb = 0; nb < 4; ++nb) {
                    uint32_t bh[4];
                    ldsm4t(bh, bbase + kk * 16 * 264 + bRowOff + nb * 16);
                    mma16816(c[nb * 2],     af0, bh[0], bh[1]);
                    mma16816(c[nb * 2 + 1], af0, bh[2], bh[3]);
                    mma16816(c[8 + nb * 2],     af1, bh[0], bh[1]);
                    mma16816(c[8 + nb * 2 + 1], af1, bh[2], bh[3]);
                }
            }
        }

        if (hasNext) {
            W8 w = wgen8(a0, a1, p0, p1, q0, q1, P1r, Q1r);
            *(uint4*)&sW[cur ^ 1][wr * 40 + wc] = w.v;
            float ssum = w.ssum, cnt = w.cnt;
            ssum += __shfl_xor_sync(0xffffffffu, ssum, 1);
            ssum += __shfl_xor_sync(0xffffffffu, ssum, 2);
            cnt  += __shfl_xor_sync(0xffffffffu, cnt, 1);
            cnt  += __shfl_xor_sync(0xffffffffu, cnt, 2);
            if ((t & 3) == 0) { sSum[wr] += ssum; sDeg[wr] += cnt; }
            CP_WAIT0();
        }
        __syncthreads();
    }

    // ---- epilogue ----
    float* ob = out + oof;
    // A-fragment rows: mgrp + [0,16) from af0, mgrp + 16 + [0,16) from af1
#pragma unroll
    for (int mt = 0; mt < 2; ++mt) {
        const int rlo = mgrp + mt * 16 + (lane >> 2);
        const int rhi = rlo + 8;
        float slo = (sDeg[rlo] > 0.f && sSum[rlo] > 0.f) ? sDeg[rlo] / sSum[rlo] : 0.f;
        float shi = (sDeg[rhi] > 0.f && sSum[rhi] > 0.f) ? sDeg[rhi] / sSum[rhi] : 0.f;
        float* olo = ob + ((size_t)b * N + n0 + rlo) * 256;
        float* ohi = ob + ((size_t)b * N + n0 + rhi) * 256;
#pragma unroll
        for (int j = 0; j < 8; ++j) {
            int nt = j >> 1;
            int half8 = j & 1;
            float* cc = c[mt * 8 + j];
            int col = ngrp + nt * 16 + half8 * 8 + (lane & 3) * 2;
            float b0 = bias[col], b1 = bias[col + 1];
            float2 v0 = make_float2(cc[0] * slo + b0, cc[1] * slo + b1);
            float2 v1 = make_float2(cc[2] * shi + b0, cc[3] * shi + b1);
            *(float2*)(olo + col) = v0;
            *(float2*)(ohi + col) = v1;
        }
    }
}

// ---------------------------------------------------------------------------
// Launch: 4 kernels total
// ---------------------------------------------------------------------------
extern "C" void kernel_launch(void* const* d_in, const int* in_sizes, int n_in,
                              void* d_out, int out_size)
{
    const float* x0   = (const float*)d_in[0];
    const float* x1   = (const float*)d_in[1];
    const float* W0   = (const float*)d_in[2];
    const float* W1   = (const float*)d_in[3];
    const float* a1_0 = (const float*)d_in[4];
    const float* a2_0 = (const float*)d_in[5];
    const float* a1_1 = (const float*)d_in[6];
    const float* a2_1 = (const float*)d_in[7];
    const float* bias = (const float*)d_in[8];
    const int* adj00  = (const int*)d_in[9];
    const int* adj01  = (const int*)d_in[10];
    const int* adj10  = (const int*)d_in[11];
    const int* adj11  = (const int*)d_in[12];
    float* out = (float*)d_out;

    const int R0 = BATCH * N1;   // 65536
    const int R1 = BATCH * N2;   // 32768

    gemm_all<<<dim3((R0 + R1) / 128, 2), 256>>>(x0, x1, W0, W1);
    edot_all<<<(R0 + R1) / 8, 256>>>(a1_0, a2_0, a1_1, a2_1);
    pqmax_all<<<4 * BATCH, 256>>>();
    att_all<<<dim3(24, BATCH), 512>>>(adj00, adj01, adj10, adj11, bias, out);
}

// round 14
// speedup vs baseline: 1.2861x; 1.0807x over previous
#include <cuda_runtime.h>
#include <cuda_fp16.h>
#include <cstdint>
#include <cstddef>

#define BATCH 64
#define N1 1024
#define N2 512
#define F0K 512
#define F1K 384

// ---------------------------------------------------------------------------
// Scratch
// ---------------------------------------------------------------------------
__device__ __half g_h0hi[(size_t)BATCH * N1 * 256];
__device__ __half g_h0lo[(size_t)BATCH * N1 * 256];
__device__ __half g_h1hi[(size_t)BATCH * N2 * 256];
__device__ __half g_h1lo[(size_t)BATCH * N2 * 256];
__device__ float g_eA[BATCH * N1];
__device__ float g_eB[BATCH * N1];
__device__ float g_eC[BATCH * N2];
__device__ float g_eD[BATCH * N2];
__device__ float g_eE[BATCH * N1];
__device__ float g_eF[BATCH * N2];
__device__ float g_mx[4 * BATCH];
__device__ __half g_P2h[2 * BATCH * (N1 + N2)];
__device__ __half g_Q2h[2 * BATCH * (N1 + N2)];

// P2/Q2 segment offsets
#define PQ_O0 ((size_t)0)
#define PQ_O1 ((size_t)BATCH * N1)
#define PQ_O2 (PQ_O1 + (size_t)BATCH * N2)
#define PQ_O3 (PQ_O2 + (size_t)BATCH * N1)
// output segment offsets
#define OO_00 ((size_t)0)
#define OO_01 ((size_t)BATCH * N1 * 256)
#define OO_10 (OO_01 + (size_t)BATCH * N1 * 256)
#define OO_11 (OO_10 + (size_t)BATCH * N2 * 256)

// ---------------------------------------------------------------------------
// mma.sync / ldmatrix / cp.async helpers (sm_80 PTX, valid at base sm_103)
// ---------------------------------------------------------------------------
__device__ __forceinline__ void ldsm4(uint32_t* d, const void* p) {
    uint32_t a = (uint32_t)__cvta_generic_to_shared(p);
    asm volatile("ldmatrix.sync.aligned.m8n8.x4.shared.b16 {%0,%1,%2,%3}, [%4];"
                 : "=r"(d[0]), "=r"(d[1]), "=r"(d[2]), "=r"(d[3]) : "r"(a));
}
__device__ __forceinline__ void ldsm4t(uint32_t* d, const void* p) {
    uint32_t a = (uint32_t)__cvta_generic_to_shared(p);
    asm volatile("ldmatrix.sync.aligned.m8n8.x4.trans.shared.b16 {%0,%1,%2,%3}, [%4];"
                 : "=r"(d[0]), "=r"(d[1]), "=r"(d[2]), "=r"(d[3]) : "r"(a));
}
__device__ __forceinline__ void mma16816(float* c, const uint32_t* a,
                                         uint32_t b0, uint32_t b1) {
    asm volatile(
        "mma.sync.aligned.m16n8k16.row.col.f32.f16.f16.f32 "
        "{%0,%1,%2,%3}, {%4,%5,%6,%7}, {%8,%9}, {%0,%1,%2,%3};"
        : "+f"(c[0]), "+f"(c[1]), "+f"(c[2]), "+f"(c[3])
        : "r"(a[0]), "r"(a[1]), "r"(a[2]), "r"(a[3]), "r"(b0), "r"(b1));
}
__device__ __forceinline__ void cp16(uint32_t dst, const void* src) {
    asm volatile("cp.async.cg.shared.global [%0], [%1], 16;"
                 :: "r"(dst), "l"(src));
}
#define CP_COMMIT() asm volatile("cp.async.commit_group;" ::: "memory")
#define CP_WAIT0()  asm volatile("cp.async.wait_group 0;" ::: "memory")

// packed-fp16 w-gen for 8 neighbors. adj values are {0,1} (randint(0,2)).
struct W8 { uint4 v; float ssum; float cnt; };
__device__ __forceinline__ W8 wgen8h(
    int4 a0, int4 a1, uint4 pv, uint4 qv, __half2 P1h, __half2 Q1h)
{
    int av[8] = {a0.x, a0.y, a0.z, a0.w, a1.x, a1.y, a1.z, a1.w};
    uint32_t pp[4] = {pv.x, pv.y, pv.z, pv.w};
    uint32_t qq[4] = {qv.x, qv.y, qv.z, qv.w};
    uint32_t wv[4];
    __half2 acc = __float2half2_rn(0.f);
    int icnt = 0;
#pragma unroll
    for (int i = 0; i < 4; ++i) {
        __half2 p2 = *reinterpret_cast<__half2*>(&pp[i]);
        __half2 q2 = *reinterpret_cast<__half2*>(&qq[i]);
        __half2 w2 = __hmax2(__hmul2(P1h, p2), __hmul2(Q1h, q2));
        uint32_t wb = *reinterpret_cast<uint32_t*>(&w2);
        uint32_t mask = (uint32_t)av[2 * i] * 0xFFFFu
                      | (uint32_t)av[2 * i + 1] * 0xFFFF0000u;
        wb &= mask;
        wv[i] = wb;
        __half2 wm = *reinterpret_cast<__half2*>(&wb);
        acc = __hadd2(acc, wm);
        icnt += av[2 * i] + av[2 * i + 1];
    }
    W8 r;
    r.v.x = wv[0]; r.v.y = wv[1]; r.v.z = wv[2]; r.v.w = wv[3];
    r.ssum = __low2float(acc) + __high2float(acc);
    r.cnt = (float)icnt;
    return r;
}

// ---------------------------------------------------------------------------
// Merged tensor-core GEMM for both inputs (3-pass fp16 split).
// ---------------------------------------------------------------------------
__global__ __launch_bounds__(256) void gemm_all(
    const float* __restrict__ x0, const float* __restrict__ x1,
    const float* __restrict__ W0, const float* __restrict__ W1)
{
    __shared__ __align__(16) __half sAhi[128 * 40];
    __shared__ __align__(16) __half sAlo[128 * 40];
    __shared__ __align__(16) __half sWhi[32 * 136];
    __shared__ __align__(16) __half sWlo[32 * 136];

    const int bx = blockIdx.x;
    const float* A; const float* W; __half* Chi; __half* Clo; int K, mblk;
    if (bx < BATCH * N1 / 128) {
        A = x0; W = W0; K = F0K; mblk = bx;
        Chi = g_h0hi; Clo = g_h0lo;
    } else {
        A = x1; W = W1; K = F1K; mblk = bx - BATCH * N1 / 128;
        Chi = g_h1hi; Clo = g_h1lo;
    }

    const int t    = threadIdx.x;
    const int lane = t & 31;
    const int wid  = t >> 5;
    const int m0   = mblk * 128;
    const int nc0  = blockIdx.y * 128;

    const int ar = t >> 1;
    const int ac = (t & 1) * 16;
    const float* Ap = A + (size_t)(m0 + ar) * K + ac;
    const int wk = t >> 3;
    const int wc = (t & 7) * 16;
    const float* Wp = W + (size_t)wk * 256 + nc0 + wc;

    const int am0 = (wid & 3) * 32;
    const int cn0 = (wid >> 2) * 64;

    float cf[16][4];
#pragma unroll
    for (int i = 0; i < 16; ++i)
#pragma unroll
        for (int j = 0; j < 4; ++j) cf[i][j] = 0.f;

    float4 avr[4], wvr[4];
#pragma unroll
    for (int j = 0; j < 4; ++j) {
        avr[j] = *(const float4*)(Ap + j * 4);
        wvr[j] = *(const float4*)(Wp + j * 4);
    }

    for (int k0 = 0; k0 < K; k0 += 32) {
#pragma unroll
        for (int j = 0; j < 4; ++j) {
            float4 v = avr[j];
            __half2 h0 = __floats2half2_rn(v.x, v.y);
            __half2 h1 = __floats2half2_rn(v.z, v.w);
            __half2 l0 = __floats2half2_rn(v.x - __low2float(h0), v.y - __high2float(h0));
            __half2 l1 = __floats2half2_rn(v.z - __low2float(h1), v.w - __high2float(h1));
            int off = ar * 40 + ac + j * 4;
            *(__half2*)&sAhi[off]     = h0;
            *(__half2*)&sAhi[off + 2] = h1;
            *(__half2*)&sAlo[off]     = l0;
            *(__half2*)&sAlo[off + 2] = l1;
            v = wvr[j];
            h0 = __floats2half2_rn(v.x, v.y);
            h1 = __floats2half2_rn(v.z, v.w);
            l0 = __floats2half2_rn(v.x - __low2float(h0), v.y - __high2float(h0));
            l1 = __floats2half2_rn(v.z - __low2float(h1), v.w - __high2float(h1));
            off = wk * 136 + wc + j * 4;
            *(__half2*)&sWhi[off]     = h0;
            *(__half2*)&sWhi[off + 2] = h1;
            *(__half2*)&sWlo[off]     = l0;
            *(__half2*)&sWlo[off + 2] = l1;
        }
        __syncthreads();

        if (k0 + 32 < K) {
#pragma unroll
            for (int j = 0; j < 4; ++j) {
                avr[j] = *(const float4*)(Ap + k0 + 32 + j * 4);
                wvr[j] = *(const float4*)(Wp + (size_t)(k0 + 32) * 256 + j * 4);
            }
        }

#pragma unroll
        for (int kk = 0; kk < 2; ++kk) {
            uint32_t ah[2][4], al[2][4];
#pragma unroll
            for (int mt = 0; mt < 2; ++mt) {
                const int arow = am0 + mt * 16 + (lane & 15);
                const int acol = kk * 16 + (lane >> 4) * 8;
                ldsm4(ah[mt], &sAhi[arow * 40 + acol]);
                ldsm4(al[mt], &sAlo[arow * 40 + acol]);
            }
#pragma unroll
            for (int nt = 0; nt < 4; ++nt) {
                uint32_t bh[4], bl[4];
                const int boff = (kk * 16 + (lane & 15)) * 136 + cn0 +
                                 nt * 16 + (lane >> 4) * 8;
                ldsm4t(bh, &sWhi[boff]);
                ldsm4t(bl, &sWlo[boff]);
#pragma unroll
                for (int mt = 0; mt < 2; ++mt) {
                    float* c0 = cf[mt * 8 + nt * 2];
                    float* c1 = cf[mt * 8 + nt * 2 + 1];
                    mma16816(c0, ah[mt], bh[0], bh[1]);
                    mma16816(c1, ah[mt], bh[2], bh[3]);
                    mma16816(c0, ah[mt], bl[0], bl[1]);
                    mma16816(c1, ah[mt], bl[2], bl[3]);
                    mma16816(c0, al[mt], bh[0], bh[1]);
                    mma16816(c1, al[mt], bh[2], bh[3]);
                }
            }
        }
        __syncthreads();
    }

    const int rlo = am0 + (lane >> 2);
#pragma unroll
    for (int mt = 0; mt < 2; ++mt) {
#pragma unroll
        for (int j = 0; j < 8; ++j) {
            int nt = j >> 1;
            int half8 = j & 1;
            float* cc = cf[mt * 8 + j];
            int row = rlo + mt * 16;
            int col = nc0 + cn0 + nt * 16 + half8 * 8 + (lane & 3) * 2;
            {
                float x = cc[0], y = cc[1];
                __half2 hi = __floats2half2_rn(x, y);
                __half2 lo = __floats2half2_rn(x - __low2float(hi), y - __high2float(hi));
                size_t off = (size_t)(m0 + row) * 256 + col;
                *(__half2*)&Chi[off] = hi;
                *(__half2*)&Clo[off] = lo;
            }
            {
                float x = cc[2], y = cc[3];
                __half2 hi = __floats2half2_rn(x, y);
                __half2 lo = __floats2half2_rn(x - __low2float(hi), y - __high2float(hi));
                size_t off = (size_t)(m0 + row + 8) * 256 + col;
                *(__half2*)&Chi[off] = hi;
                *(__half2*)&Clo[off] = lo;
            }
        }
    }
}

// ---------------------------------------------------------------------------
// Merged triple dot over both h tensors
// ---------------------------------------------------------------------------
__global__ __launch_bounds__(256) void edot_all(
    const float* __restrict__ a1_0, const float* __restrict__ a2_0,
    const float* __restrict__ a1_1, const float* __restrict__ a2_1)
{
    const int gr = blockIdx.x * 8 + (threadIdx.x >> 5);
    const int lane = threadIdx.x & 31;
    const __half *ph, *pl;
    const float *v0, *v1, *v2;
    float *e0, *e1, *e2;
    int r;
    if (gr < BATCH * N1) {
        r = gr;
        ph = g_h0hi + (size_t)r * 256; pl = g_h0lo + (size_t)r * 256;
        v0 = a1_0; v1 = a2_0; v2 = a2_1;
        e0 = g_eA; e1 = g_eB; e2 = g_eE;
    } else {
        r = gr - BATCH * N1;
        ph = g_h1hi + (size_t)r * 256; pl = g_h1lo + (size_t)r * 256;
        v0 = a2_0; v1 = a1_1; v2 = a2_1;
        e0 = g_eC; e1 = g_eD; e2 = g_eF;
    }
    float s0 = 0.f, s1 = 0.f, s2 = 0.f;
#pragma unroll
    for (int i = 0; i < 8; ++i) {
        int c = lane + i * 32;
        float x = __half2float(ph[c]) + __half2float(pl[c]);
        s0 += x * v0[c];
        s1 += x * v1[c];
        s2 += x * v2[c];
    }
#pragma unroll
    for (int o = 16; o > 0; o >>= 1) {
        s0 += __shfl_xor_sync(0xffffffffu, s0, o);
        s1 += __shfl_xor_sync(0xffffffffu, s1, o);
        s2 += __shfl_xor_sync(0xffffffffu, s2, o);
    }
    if (lane == 0) { e0[r] = s0; e1[r] = s1; e2[r] = s2; }
}

// ---------------------------------------------------------------------------
// Merged per-batch max + P2/Q2 (fp16) generation
// ---------------------------------------------------------------------------
__global__ __launch_bounds__(256) void pqmax_all()
{
    __shared__ float red[256];
    const int blk = blockIdx.x >> 6;
    const int b   = blockIdx.x & 63;
    const int t   = threadIdx.x;
    const float* p; int M; size_t off;
    if (blk == 0)      { p = g_eB; M = N1; off = PQ_O0; }
    else if (blk == 1) { p = g_eC; M = N2; off = PQ_O1; }
    else if (blk == 2) { p = g_eE; M = N1; off = PQ_O2; }
    else               { p = g_eF; M = N2; off = PQ_O3; }
    p += (size_t)b * M;
    float m = -3.4e38f;
    for (int i = t; i < M; i += 256) m = fmaxf(m, p[i]);
    red[t] = m;
    __syncthreads();
    for (int s = 128; s > 0; s >>= 1) {
        if (t < s) red[t] = fmaxf(red[t], red[t + s]);
        __syncthreads();
    }
    const float mx = red[0];
    if (t == 0) g_mx[blk * BATCH + b] = mx;
    __half* P = g_P2h + off + (size_t)b * M;
    __half* Q = g_Q2h + off + (size_t)b * M;
    for (int i = t; i < M; i += 256) {
        float d = p[i] - mx;
        P[i] = __float2half_rn(__expf(d));
        Q[i] = __float2half_rn(__expf(0.2f * d));
    }
}

// ---------------------------------------------------------------------------
// Merged fused masked attention, 2-stage ping-pong.
// 128-row CTAs, 512 threads (16 warps, 4m x 4n warp map). fp16 wgen path.
// ---------------------------------------------------------------------------
__global__ __launch_bounds__(512, 1) void att_all(
    const int* __restrict__ adj00, const int* __restrict__ adj01,
    const int* __restrict__ adj10, const int* __restrict__ adj11,
    const float* __restrict__ bias, float* __restrict__ out)
{
    __shared__ __align__(16) __half sW[2][128 * 40];   // 20480 B
    __shared__ __align__(16) __half sB[2][32 * 264];   // 33792 B
    __shared__ float sP1[128], sQ1[128], sSum[128], sDeg[128];

    const int bx = blockIdx.x;   // 8 blk00 | 4 blk10 | 8 blk01 | 4 blk11
    const int b  = blockIdx.y;
    const __half* g; const int* adjB; const float* e1B;
    int mxi, N, M, tl; size_t pqo, oof;
    if (bx < 8) {
        tl = bx;      g = g_h0hi; adjB = adj00; e1B = g_eA; mxi = 0;
        pqo = PQ_O0; oof = OO_00; N = N1; M = N1;
    } else if (bx < 12) {
        tl = bx - 8;  g = g_h0hi; adjB = adj10; e1B = g_eD; mxi = 2;
        pqo = PQ_O2; oof = OO_10; N = N2; M = N1;
    } else if (bx < 20) {
        tl = bx - 12; g = g_h1hi; adjB = adj01; e1B = g_eA; mxi = 1;
        pqo = PQ_O1; oof = OO_01; N = N1; M = N2;
    } else {
        tl = bx - 20; g = g_h1hi; adjB = adj11; e1B = g_eD; mxi = 3;
        pqo = PQ_O3; oof = OO_11; N = N2; M = N2;
    }
    const int n0 = tl * 128;

    const int t    = threadIdx.x;
    const int lane = t & 31;
    const int wid  = t >> 5;

    if (t < 128) {
        float v = e1B[(size_t)b * N + n0 + t] + g_mx[mxi * BATCH + b];
        float sh = fmaxf(v, 0.2f * v);
        sP1[t] = __expf(v - sh);
        sQ1[t] = __expf(0.2f * v - sh);
        sSum[t] = 0.f;
        sDeg[t] = 0.f;
    }
    __syncthreads();

    float c[16][4];
#pragma unroll
    for (int i = 0; i < 16; ++i)
#pragma unroll
        for (int j = 0; j < 4; ++j) c[i][j] = 0.f;

    // g tile cp.async: row k = t>>4 (32 rows), cols (t&15)*16 .. +15 (2x16B)
    const int bk = t >> 4;
    const int bc = (t & 15) * 16;
    const __half* gsrc = g + ((size_t)b * M + bk) * 256 + bc;
    const uint32_t sb0 = (uint32_t)__cvta_generic_to_shared(&sB[0][bk * 264 + bc]);
    const uint32_t sb1 = (uint32_t)__cvta_generic_to_shared(&sB[1][bk * 264 + bc]);

    // w-gen: row r = t>>2 (0..127), cols (t&3)*8 .. +7
    const int wr = t >> 2;
    const int wc = (t & 3) * 8;
    const int* adjp = adjB + ((size_t)b * N + n0 + wr) * M + wc;
    const __half* p2p = g_P2h + pqo + (size_t)b * M + wc;
    const __half* q2p = g_Q2h + pqo + (size_t)b * M + wc;
    const __half2 P1h = __float2half2_rn(sP1[wr]);
    const __half2 Q1h = __float2half2_rn(sQ1[wr]);

    // MMA mapping: warp = (wid&3) m-group (32 rows) x (wid>>2) n-group (64 cols)
    const int mgrp = (wid & 3) * 32;
    const int ngrp = (wid >> 2) * 64;
    const int aOff0 = (mgrp + (lane & 15)) * 40 + (lane >> 4) * 8;
    const int aOff1 = aOff0 + 16 * 40;
    const int bRowOff = (lane & 15) * 264 + ngrp + (lane >> 4) * 8;

    const int iters = M >> 5;

    // ---- prolog: stage chunk 0 ----
    {
#pragma unroll
        for (int j = 0; j < 2; ++j) cp16(sb0 + j * 16, gsrc + j * 8);
        CP_COMMIT();
        int4 a0 = *(const int4*)(adjp);
        int4 a1 = *(const int4*)(adjp + 4);
        uint4 pv = *(const uint4*)(p2p);
        uint4 qv = *(const uint4*)(q2p);
        W8 w = wgen8h(a0, a1, pv, qv, P1h, Q1h);
        *(uint4*)&sW[0][wr * 40 + wc] = w.v;
        float ssum = w.ssum, cnt = w.cnt;
        ssum += __shfl_xor_sync(0xffffffffu, ssum, 1);
        ssum += __shfl_xor_sync(0xffffffffu, ssum, 2);
        cnt  += __shfl_xor_sync(0xffffffffu, cnt, 1);
        cnt  += __shfl_xor_sync(0xffffffffu, cnt, 2);
        if ((t & 3) == 0) { sSum[wr] += ssum; sDeg[wr] += cnt; }
        CP_WAIT0();
    }
    __syncthreads();

    for (int it = 0; it < iters; ++it) {
        const int cur = it & 1;
        const bool hasNext = (it + 1) < iters;
        int4 a0, a1; uint4 pv, qv;

        if (hasNext) {
            const int m1 = (it + 1) * 32;
            const uint32_t sbn = (cur ^ 1) ? sb1 : sb0;
#pragma unroll
            for (int j = 0; j < 2; ++j)
                cp16(sbn + j * 16, gsrc + (size_t)m1 * 256 + j * 8);
            CP_COMMIT();
            a0 = *(const int4*)(adjp + m1);
            a1 = *(const int4*)(adjp + m1 + 4);
            pv = *(const uint4*)(p2p + m1);
            qv = *(const uint4*)(q2p + m1);
        }

        // ---- MMA from buffer cur ----
        {
            const __half* wbase = &sW[cur][0];
            const __half* bbase = &sB[cur][0];
#pragma unroll
            for (int kk = 0; kk < 2; ++kk) {
                uint32_t af0[4], af1[4];
                ldsm4(af0, wbase + aOff0 + kk * 16);
                ldsm4(af1, wbase + aOff1 + kk * 16);
#pragma unroll
                for (int nb = 0; nb < 4; ++nb) {
                    uint32_t bh[4];
                    ldsm4t(bh, bbase + kk * 16 * 264 + bRowOff + nb * 16);
                    mma16816(c[nb * 2],     af0, bh[0], bh[1]);
                    mma16816(c[nb * 2 + 1], af0, bh[2], bh[3]);
                    mma16816(c[8 + nb * 2],     af1, bh[0], bh[1]);
                    mma16816(c[8 + nb * 2 + 1], af1, bh[2], bh[3]);
                }
            }
        }

        if (hasNext) {
            W8 w = wgen8h(a0, a1, pv, qv, P1h, Q1h);
            *(uint4*)&sW[cur ^ 1][wr * 40 + wc] = w.v;
            float ssum = w.ssum, cnt = w.cnt;
            ssum += __shfl_xor_sync(0xffffffffu, ssum, 1);
            ssum += __shfl_xor_sync(0xffffffffu, ssum, 2);
            cnt  += __shfl_xor_sync(0xffffffffu, cnt, 1);
            cnt  += __shfl_xor_sync(0xffffffffu, cnt, 2);
            if ((t & 3) == 0) { sSum[wr] += ssum; sDeg[wr] += cnt; }
            CP_WAIT0();
        }
        __syncthreads();
    }

    // ---- epilogue ----
    float* ob = out + oof;
#pragma unroll
    for (int mt = 0; mt < 2; ++mt) {
        const int rlo = mgrp + mt * 16 + (lane >> 2);
        const int rhi = rlo + 8;
        float slo = (sDeg[rlo] > 0.f && sSum[rlo] > 0.f) ? sDeg[rlo] / sSum[rlo] : 0.f;
        float shi = (sDeg[rhi] > 0.f && sSum[rhi] > 0.f) ? sDeg[rhi] / sSum[rhi] : 0.f;
        float* olo = ob + ((size_t)b * N + n0 + rlo) * 256;
        float* ohi = ob + ((size_t)b * N + n0 + rhi) * 256;
#pragma unroll
        for (int j = 0; j < 8; ++j) {
            int nt = j >> 1;
            int half8 = j & 1;
            float* cc = c[mt * 8 + j];
            int col = ngrp + nt * 16 + half8 * 8 + (lane & 3) * 2;
            float b0 = bias[col], b1 = bias[col + 1];
            float2 v0 = make_float2(cc[0] * slo + b0, cc[1] * slo + b1);
            float2 v1 = make_float2(cc[2] * shi + b0, cc[3] * shi + b1);
            *(float2*)(olo + col) = v0;
            *(float2*)(ohi + col) = v1;
        }
    }
}

// ---------------------------------------------------------------------------
// Launch: 4 kernels total
// ---------------------------------------------------------------------------
extern "C" void kernel_launch(void* const* d_in, const int* in_sizes, int n_in,
                              void* d_out, int out_size)
{
    const float* x0   = (const float*)d_in[0];
    const float* x1   = (const float*)d_in[1];
    const float* W0   = (const float*)d_in[2];
    const float* W1   = (const float*)d_in[3];
    const float* a1_0 = (const float*)d_in[4];
    const float* a2_0 = (const float*)d_in[5];
    const float* a1_1 = (const float*)d_in[6];
    const float* a2_1 = (const float*)d_in[7];
    const float* bias = (const float*)d_in[8];
    const int* adj00  = (const int*)d_in[9];
    const int* adj01  = (const int*)d_in[10];
    const int* adj10  = (const int*)d_in[11];
    const int* adj11  = (const int*)d_in[12];
    float* out = (float*)d_out;

    const int R0 = BATCH * N1;   // 65536
    const int R1 = BATCH * N2;   // 32768

    gemm_all<<<dim3((R0 + R1) / 128, 2), 256>>>(x0, x1, W0, W1);
    edot_all<<<(R0 + R1) / 8, 256>>>(a1_0, a2_0, a1_1, a2_1);
    pqmax_all<<<4 * BATCH, 256>>>();
    att_all<<<dim3(24, BATCH), 512>>>(adj00, adj01, adj10, adj11, bias, out);
}